// round 5
// baseline (speedup 1.0000x reference)
#include <cuda_runtime.h>
#include <cstdint>

typedef unsigned long long ull;

#define SEQ   2048
#define NH    16
#define NB    2
#define HD    64
#define QB    128
#define KBT   128
#define NKT   (SEQ / KBT)

// Scratch for projected Q/K/V in [b,h,s,d] layout
__device__ float g_q[NB * NH * SEQ * HD];
__device__ float g_k[NB * NH * SEQ * HD];
__device__ float g_v[NB * NH * SEQ * HD];

// ---------------------------------------------------------------------------
// JAX threefry2x32 (partitionable): key=(0,42), counts=(0,i), bits = x0^x1
// ---------------------------------------------------------------------------
__device__ __forceinline__ unsigned threefry_bits(unsigned c1)
{
    const unsigned K1 = 42u;
    const unsigned K2 = 0x1BD11BF0u;
    unsigned x0 = 0u;
    unsigned x1 = c1 + K1;
#define TFR(r) { x0 += x1; x1 = __funnelshift_l(x1, x1, (r)); x1 ^= x0; }
    TFR(13); TFR(15); TFR(26); TFR(6);
    x0 += K1; x1 += K2 + 1u;
    TFR(17); TFR(29); TFR(16); TFR(24);
    x0 += K2; x1 += 2u;
    TFR(13); TFR(15); TFR(26); TFR(6);
    x1 += K1 + 3u;
    TFR(17); TFR(29); TFR(16); TFR(24);
    x0 += K1; x1 += K2 + 4u;
    TFR(13); TFR(15); TFR(26); TFR(6);
    x0 += K2; x1 += 5u;
#undef TFR
    return x0 ^ x1;
}

// ---------------------------------------------------------------------------
// packed f32x2 helpers
// ---------------------------------------------------------------------------
__device__ __forceinline__ ull pack2(float a, float b) {
    ull r; asm("mov.b64 %0, {%1,%2};" : "=l"(r) : "f"(a), "f"(b)); return r;
}
__device__ __forceinline__ void unpack2(ull v, float& a, float& b) {
    asm("mov.b64 {%0,%1}, %2;" : "=f"(a), "=f"(b) : "l"(v));
}
__device__ __forceinline__ void ffma2(ull& d, ull a, ull b) {
    asm("fma.rn.f32x2 %0, %1, %2, %0;" : "+l"(d) : "l"(a), "l"(b));
}
__device__ __forceinline__ void lds2(ull& a, ull& b, uint32_t addr) {
    asm volatile("ld.shared.v2.b64 {%0,%1}, [%2];" : "=l"(a), "=l"(b) : "r"(addr));
}
__device__ __forceinline__ float shflmax16(float v) {
    v = fmaxf(v, __shfl_xor_sync(0xffffffffu, v, 1));
    v = fmaxf(v, __shfl_xor_sync(0xffffffffu, v, 2));
    v = fmaxf(v, __shfl_xor_sync(0xffffffffu, v, 4));
    v = fmaxf(v, __shfl_xor_sync(0xffffffffu, v, 8));
    return v;
}
__device__ __forceinline__ float shflsum16(float v) {
    v += __shfl_xor_sync(0xffffffffu, v, 1);
    v += __shfl_xor_sync(0xffffffffu, v, 2);
    v += __shfl_xor_sync(0xffffffffu, v, 4);
    v += __shfl_xor_sync(0xffffffffu, v, 8);
    return v;
}

// ---------------------------------------------------------------------------
// Projection (unchanged, proven): out[b,h,s,e] = sum_d in[b,s,h,d]*W[e,d] + b[e]
// ---------------------------------------------------------------------------
__global__ void __launch_bounds__(256) proj_kernel(
    const float* __restrict__ q_in, const float* __restrict__ k_in, const float* __restrict__ v_in,
    const float* __restrict__ Wq, const float* __restrict__ bq,
    const float* __restrict__ Wk, const float* __restrict__ bk,
    const float* __restrict__ Wv, const float* __restrict__ bv)
{
    __shared__ float Wt[64 * 68];
    __shared__ float It[64 * 68];
    __shared__ float bs[64];

    const int which = blockIdx.y;
    const float* in  = (which == 0) ? q_in : (which == 1) ? k_in : v_in;
    const float* W   = (which == 0) ? Wq  : (which == 1) ? Wk  : Wv;
    const float* bia = (which == 0) ? bq  : (which == 1) ? bk  : bv;
    float* outp      = (which == 0) ? g_q : (which == 1) ? g_k : g_v;

    const int tid = threadIdx.x;
    const int row0 = blockIdx.x * 64;

    if (tid < 64) bs[tid] = bia[tid];
    for (int i = tid; i < 1024; i += 256) {
        int r = i >> 4, c4 = (i & 15) << 2;
        float4 w = *(const float4*)(W + r * 64 + c4);
        Wt[(c4 + 0) * 68 + r] = w.x; Wt[(c4 + 1) * 68 + r] = w.y;
        Wt[(c4 + 2) * 68 + r] = w.z; Wt[(c4 + 3) * 68 + r] = w.w;
        float4 x = *(const float4*)(in + (size_t)(row0 + r) * 64 + c4);
        It[(c4 + 0) * 68 + r] = x.x; It[(c4 + 1) * 68 + r] = x.y;
        It[(c4 + 2) * 68 + r] = x.z; It[(c4 + 3) * 68 + r] = x.w;
    }
    __syncthreads();

    const int ty = tid >> 4, tx = tid & 15;
    float acc[4][4];
#pragma unroll
    for (int i = 0; i < 4; i++) { acc[i][0] = acc[i][1] = acc[i][2] = acc[i][3] = 0.0f; }

#pragma unroll 16
    for (int d = 0; d < 64; d++) {
        float4 a = *(const float4*)(It + d * 68 + 4 * ty);
        float4 w = *(const float4*)(Wt + d * 68 + 4 * tx);
        acc[0][0] += a.x * w.x; acc[0][1] += a.x * w.y; acc[0][2] += a.x * w.z; acc[0][3] += a.x * w.w;
        acc[1][0] += a.y * w.x; acc[1][1] += a.y * w.y; acc[1][2] += a.y * w.z; acc[1][3] += a.y * w.w;
        acc[2][0] += a.z * w.x; acc[2][1] += a.z * w.y; acc[2][2] += a.z * w.z; acc[2][3] += a.z * w.w;
        acc[3][0] += a.w * w.x; acc[3][1] += a.w * w.y; acc[3][2] += a.w * w.z; acc[3][3] += a.w * w.w;
    }

    float4 bb = *(const float4*)(bs + 4 * tx);
#pragma unroll
    for (int i = 0; i < 4; i++) {
        int r  = row0 + 4 * ty + i;
        int hh = r & 15;
        int ss = (r >> 4) & 2047;
        int bI = r >> 15;
        float4 res;
        res.x = acc[i][0] + bb.x; res.y = acc[i][1] + bb.y;
        res.z = acc[i][2] + bb.z; res.w = acc[i][3] + bb.w;
        *(float4*)(outp + ((size_t)((bI * NH + hh) * SEQ + ss)) * HD + 4 * tx) = res;
    }
}

// ---------------------------------------------------------------------------
// Flash attention: 128x128 tile, 8x8 per thread, FFMA2 QK with pre-dup'd Q.
// grid = (16 s-tiles, 16 heads, 2 batches), 256 threads.
// smem: Qdup[64][130](ull) | Kt[64][132] | Vs[128][68] | Ps[128][132]
// ---------------------------------------------------------------------------
#define OFF_KT   66560
#define OFF_VS   100352
#define OFF_PS   135168
#define SMEM_SZ  202752

__global__ void __launch_bounds__(256, 1) attn_kernel(const float* __restrict__ mask,
                                                      const float* __restrict__ inv_scale_p,
                                                      float* __restrict__ out)
{
    extern __shared__ char smem_raw[];
    ull*   Qd = (ull*)smem_raw;                      // [64][130] (q,q) pairs
    float* Kt = (float*)(smem_raw + OFF_KT);         // [64][132] d-major
    float* Vs = (float*)(smem_raw + OFF_VS);         // [128][68] natural
    float* Ps = (float*)(smem_raw + OFF_PS);         // [128][132] row-major

    const uint32_t QdA = (uint32_t)__cvta_generic_to_shared(Qd);
    const uint32_t KtA = (uint32_t)__cvta_generic_to_shared(Kt);

    const int st = blockIdx.x, h = blockIdx.y, b = blockIdx.z;
    const int s0 = st * QB;
    const int tid = threadIdx.x;
    const int tx = tid & 15, ty = tid >> 4;

    const float* Qg = g_q + ((size_t)((b * NH + h) * SEQ + s0)) * HD;
    const float* Kg = g_k + ((size_t)((b * NH + h) * SEQ)) * HD;
    const float* Vg = g_v + ((size_t)((b * NH + h) * SEQ)) * HD;
    const float* Mg = mask + ((size_t)(b * SEQ + s0)) * SEQ;
    const float scale = 1.0f / inv_scale_p[0];

    // ---- fill Qdup: Qd[d][row] = (q,q) ----
    for (int i = tid; i < 2048; i += 256) {
        int c4i = i & 15, r = i >> 4;
        float4 x = *(const float4*)(Qg + r * HD + 4 * c4i);
        Qd[(4 * c4i + 0) * 130 + r] = pack2(x.x, x.x);
        Qd[(4 * c4i + 1) * 130 + r] = pack2(x.y, x.y);
        Qd[(4 * c4i + 2) * 130 + r] = pack2(x.z, x.z);
        Qd[(4 * c4i + 3) * 130 + r] = pack2(x.w, x.w);
    }

    float m_r[8], l_r[8], o[8][4];
#pragma unroll
    for (int i = 0; i < 8; i++) {
        m_r[i] = -3.0e38f; l_r[i] = 0.0f;
        o[i][0] = o[i][1] = o[i][2] = o[i][3] = 0.0f;
    }

    const unsigned hs_base = (unsigned)((b * NH + h) * SEQ + s0);

    for (int kt = 0; kt < NKT; kt++) {
        __syncthreads();   // prev PV done reading Vs/Ps; Q fill done on first iter

        // ---- fill K (d-major) + V (natural) ----
        const float* Kg_t = Kg + (size_t)kt * KBT * HD;
        const float* Vg_t = Vg + (size_t)kt * KBT * HD;
        for (int i = tid; i < 2048; i += 256) {
            int c4i = i & 15, r = i >> 4;
            float4 kx = *(const float4*)(Kg_t + r * HD + 4 * c4i);
            Kt[(4 * c4i + 0) * 132 + r] = kx.x;
            Kt[(4 * c4i + 1) * 132 + r] = kx.y;
            Kt[(4 * c4i + 2) * 132 + r] = kx.z;
            Kt[(4 * c4i + 3) * 132 + r] = kx.w;
            float4 vx = *(const float4*)(Vg_t + r * HD + 4 * c4i);
            *(float4*)(Vs + r * 68 + 4 * c4i) = vx;
        }
        __syncthreads();

        // ---- S = Q @ K^T  (FFMA2, col-pairs) ----
        // thread cols: {4tx..4tx+3, 64+4tx..64+4tx+3}; rows: 8ty..8ty+7
        ull s2[8][4];
#pragma unroll
        for (int i = 0; i < 8; i++) { s2[i][0] = 0; s2[i][1] = 0; s2[i][2] = 0; s2[i][3] = 0; }

#pragma unroll 8
        for (int d = 0; d < 64; d++) {
            ull qa[8], kb[4];
            uint32_t qaddr = QdA + (uint32_t)(d * 130 + 8 * ty) * 8u;
            lds2(qa[0], qa[1], qaddr);
            lds2(qa[2], qa[3], qaddr + 16);
            lds2(qa[4], qa[5], qaddr + 32);
            lds2(qa[6], qa[7], qaddr + 48);
            uint32_t kaddr = KtA + (uint32_t)(d * 132 + 4 * tx) * 4u;
            lds2(kb[0], kb[1], kaddr);
            lds2(kb[2], kb[3], kaddr + 256);
#pragma unroll
            for (int i = 0; i < 8; i++) {
                ffma2(s2[i][0], qa[i], kb[0]);
                ffma2(s2[i][1], qa[i], kb[1]);
                ffma2(s2[i][2], qa[i], kb[2]);
                ffma2(s2[i][3], qa[i], kb[3]);
            }
        }

        // ---- scale + mask + online softmax + dropout + P store ----
        const int t0 = kt * KBT;
#pragma unroll
        for (int i = 0; i < 8; i++) {
            const int row = 8 * ty + i;
            float x0, x1, x2, x3, x4, x5, x6, x7;
            unpack2(s2[i][0], x0, x1); unpack2(s2[i][1], x2, x3);
            unpack2(s2[i][2], x4, x5); unpack2(s2[i][3], x6, x7);

            const float* mrow = Mg + (size_t)row * SEQ + t0 + 4 * tx;
            float4 mv0 = *(const float4*)(mrow);
            float4 mv1 = *(const float4*)(mrow + 64);
            x0 = fmaf(x0, scale, mv0.x); x1 = fmaf(x1, scale, mv0.y);
            x2 = fmaf(x2, scale, mv0.z); x3 = fmaf(x3, scale, mv0.w);
            x4 = fmaf(x4, scale, mv1.x); x5 = fmaf(x5, scale, mv1.y);
            x6 = fmaf(x6, scale, mv1.z); x7 = fmaf(x7, scale, mv1.w);

            float mt = fmaxf(fmaxf(fmaxf(x0, x1), fmaxf(x2, x3)),
                             fmaxf(fmaxf(x4, x5), fmaxf(x6, x7)));
            mt = shflmax16(mt);
            float mnew = fmaxf(m_r[i], mt);
            float cf   = __expf(m_r[i] - mnew);
            m_r[i] = mnew;

            const unsigned idx0 = (hs_base + (unsigned)row) * (unsigned)SEQ
                                + (unsigned)(t0 + 4 * tx);
            const unsigned idx1 = idx0 + 64u;

            float p0 = __expf(x0 - mnew), p1 = __expf(x1 - mnew);
            float p2 = __expf(x2 - mnew), p3 = __expf(x3 - mnew);
            float p4 = __expf(x4 - mnew), p5 = __expf(x5 - mnew);
            float p6 = __expf(x6 - mnew), p7 = __expf(x7 - mnew);
            float rs = ((p0 + p1) + (p2 + p3)) + ((p4 + p5) + (p6 + p7));

            // dropout: keep iff u < 0.9, u = bitcast((bits>>9)|0x3f800000)-1
            unsigned b0 = threefry_bits(idx0 + 0), b1 = threefry_bits(idx0 + 1);
            unsigned b2 = threefry_bits(idx0 + 2), b3 = threefry_bits(idx0 + 3);
            unsigned b4 = threefry_bits(idx1 + 0), b5 = threefry_bits(idx1 + 1);
            unsigned b6 = threefry_bits(idx1 + 2), b7 = threefry_bits(idx1 + 3);
            const float is = 1.0f / 0.9f;
#define KEEP(bb, pp) ((__uint_as_float(((bb) >> 9) | 0x3f800000u) - 1.0f) < 0.9f ? (pp) * is : 0.0f)
            x0 = KEEP(b0, p0); x1 = KEEP(b1, p1); x2 = KEEP(b2, p2); x3 = KEEP(b3, p3);
            x4 = KEEP(b4, p4); x5 = KEEP(b5, p5); x6 = KEEP(b6, p6); x7 = KEEP(b7, p7);
#undef KEEP

            rs = shflsum16(rs);
            l_r[i] = l_r[i] * cf + rs;
            o[i][0] *= cf; o[i][1] *= cf; o[i][2] *= cf; o[i][3] *= cf;

            float4 w0; w0.x = x0; w0.y = x1; w0.z = x2; w0.w = x3;
            float4 w1; w1.x = x4; w1.y = x5; w1.z = x6; w1.w = x7;
            *(float4*)(Ps + row * 132 + 4 * tx)      = w0;
            *(float4*)(Ps + row * 132 + 64 + 4 * tx) = w1;
        }
        __syncthreads();   // P + V visible to all

        // ---- O += P @ V  (t-chunks of 4; P reads broadcast, V 2-phase) ----
#pragma unroll 2
        for (int tc = 0; tc < 32; tc++) {
            float4 v0 = *(const float4*)(Vs + (4 * tc + 0) * 68 + 4 * tx);
            float4 v1 = *(const float4*)(Vs + (4 * tc + 1) * 68 + 4 * tx);
            float4 v2 = *(const float4*)(Vs + (4 * tc + 2) * 68 + 4 * tx);
            float4 v3 = *(const float4*)(Vs + (4 * tc + 3) * 68 + 4 * tx);
#pragma unroll
            for (int i = 0; i < 8; i++) {
                float4 p = *(const float4*)(Ps + (8 * ty + i) * 132 + 4 * tc);
                o[i][0] += p.x * v0.x; o[i][1] += p.x * v0.y; o[i][2] += p.x * v0.z; o[i][3] += p.x * v0.w;
                o[i][0] += p.y * v1.x; o[i][1] += p.y * v1.y; o[i][2] += p.y * v1.z; o[i][3] += p.y * v1.w;
                o[i][0] += p.z * v2.x; o[i][1] += p.z * v2.y; o[i][2] += p.z * v2.z; o[i][3] += p.z * v2.w;
                o[i][0] += p.w * v3.x; o[i][1] += p.w * v3.y; o[i][2] += p.w * v3.z; o[i][3] += p.w * v3.w;
            }
        }
    }

    // ---- epilogue: normalize + store [b,h,s,e] ----
#pragma unroll
    for (int i = 0; i < 8; i++) {
        float invl = 1.0f / l_r[i];
        float4 r;
        r.x = o[i][0] * invl; r.y = o[i][1] * invl;
        r.z = o[i][2] * invl; r.w = o[i][3] * invl;
        *(float4*)(out + ((size_t)((b * NH + h) * SEQ + s0 + 8 * ty + i)) * HD + 4 * tx) = r;
    }
}

// ---------------------------------------------------------------------------
extern "C" void kernel_launch(void* const* d_in, const int* in_sizes, int n_in,
                              void* d_out, int out_size)
{
    const float* query = (const float*)d_in[0];
    const float* key_  = (const float*)d_in[1];
    const float* value = (const float*)d_in[2];
    const float* amask = (const float*)d_in[3];
    const float* invsc = (const float*)d_in[4];
    const float* Wq = (const float*)d_in[5];
    const float* bq = (const float*)d_in[6];
    const float* Wk = (const float*)d_in[7];
    const float* bk = (const float*)d_in[8];
    const float* Wv = (const float*)d_in[9];
    const float* bv = (const float*)d_in[10];
    float* out = (float*)d_out;

    (void)in_sizes; (void)n_in; (void)out_size;

    proj_kernel<<<dim3(1024, 3), 256>>>(query, key_, value, Wq, bq, Wk, bk, Wv, bv);

    cudaFuncSetAttribute(attn_kernel, cudaFuncAttributeMaxDynamicSharedMemorySize, SMEM_SZ);
    attn_kernel<<<dim3(SEQ / QB, NH, NB), 256, SMEM_SZ>>>(amask, invsc, out);
}